// round 1
// baseline (speedup 1.0000x reference)
#include <cuda_runtime.h>

// LSTMModel: 2-layer LSTM (B=2048, T=512, I=1, H=50) + FC(50->1).
// Strategy: persistent batch-partitioned CTAs. 128 CTAs x 16 batch lanes,
// 800 threads/CTA (thread = (b in [0,16), k in [0,50))). All weights + x-tile
// in SMEM; h1/h2 in SMEM; c1/c2 in registers. No global sync, no multi-launch.

#define HID   50
#define BT    16          // batch tile per CTA
#define WS    52          // padded weight row stride (even, conflict-free)
#define HS    54          // padded h row stride (even, conflict-free for 16 lanes)
#define NTH   800         // 16 * 50
#define SEQL  512
#define NBATCH 2048

__device__ __forceinline__ float ftanh(float v) {
    float y;
    asm("tanh.approx.f32 %0, %1;" : "=f"(y) : "f"(v));
    return y;
}
__device__ __forceinline__ float fsigm(float v) {
    return fmaf(0.5f, ftanh(0.5f * v), 0.5f);
}

__global__ __launch_bounds__(NTH, 1)
void lstm2_kernel(const float* __restrict__ x,
                  const float* __restrict__ W_ih0, const float* __restrict__ W_hh0,
                  const float* __restrict__ b_ih0, const float* __restrict__ b_hh0,
                  const float* __restrict__ W_ih1, const float* __restrict__ W_hh1,
                  const float* __restrict__ b_ih1, const float* __restrict__ b_hh1,
                  const float* __restrict__ fc_W, const float* __restrict__ fc_b,
                  float* __restrict__ out)
{
    extern __shared__ float sm[];
    float* sW0  = sm;                    // W_hh0  [200][WS]
    float* sWi1 = sW0  + 200 * WS;       // W_ih1  [200][WS]
    float* sWh1 = sWi1 + 200 * WS;       // W_hh1  [200][WS]
    float* sX   = sWh1 + 200 * WS;       // x tile [BT][SEQL]
    float* h1s  = sX   + BT * SEQL;      // [BT][HS]
    float* h2s  = h1s  + BT * HS;        // [BT][HS]

    const int tid = threadIdx.x;
    const int b   = tid & 15;            // batch lane in tile
    const int k   = tid >> 4;            // hidden index 0..49
    const int bg  = blockIdx.x * BT;

    // ---- prologue: stage weights and x tile into SMEM ----
    for (int i = tid; i < 200 * HID; i += NTH) {
        int r = i / HID, c = i - r * HID;
        sW0 [r * WS + c] = W_hh0[i];
        sWi1[r * WS + c] = W_ih1[i];
        sWh1[r * WS + c] = W_hh1[i];
    }
    for (int i = tid; i < BT * SEQL; i += NTH) {
        int bl = i >> 9;
        int t  = i & (SEQL - 1);
        sX[i] = x[(size_t)(bg + bl) * SEQL + t];
    }
    for (int i = tid; i < 2 * BT * HS; i += NTH) h1s[i] = 0.0f;  // h1s+h2s contiguous

    // per-thread constants: input weight (I=1) and fused biases for its 4 gate rows
    float wi0[4], bs0[4], bs1[4];
    #pragma unroll
    for (int g = 0; g < 4; g++) {
        int r = g * HID + k;
        wi0[g] = W_ih0[r];
        bs0[g] = b_ih0[r] + b_hh0[r];
        bs1[g] = b_ih1[r] + b_hh1[r];
    }
    float c1 = 0.0f, c2 = 0.0f;
    __syncthreads();

    const float2* h1v  = (const float2*)(h1s  + b * HS);
    const float2* h2v  = (const float2*)(h2s  + b * HS);
    const float2* w0k  = (const float2*)(sW0  + k * WS);
    const float2* wi1k = (const float2*)(sWi1 + k * WS);
    const float2* wh1k = (const float2*)(sWh1 + k * WS);
    const int GS = HID * WS / 2;   // float2 stride between gate blocks (1300)
    const float* sxb = sX + b * SEQL;

    for (int t = 0; t < SEQL; t++) {
        float xt  = sxb[t];
        float a10 = fmaf(xt, wi0[0], bs0[0]);
        float a11 = fmaf(xt, wi0[1], bs0[1]);
        float a12 = fmaf(xt, wi0[2], bs0[2]);
        float a13 = fmaf(xt, wi0[3], bs0[3]);
        float a20 = bs1[0], a21 = bs1[1], a22 = bs1[2], a23 = bs1[3];

        // Phase A: layer-1 recurrent matvec (h1_prev) + layer-2 recurrent matvec (h2_prev)
        #pragma unroll 5
        for (int kk = 0; kk < HID / 2; kk++) {
            float2 hv1 = h1v[kk];
            float2 hv2 = h2v[kk];
            float2 w;
            w = w0k [kk];          a10 = fmaf(w.x, hv1.x, a10); a10 = fmaf(w.y, hv1.y, a10);
            w = w0k [GS     + kk]; a11 = fmaf(w.x, hv1.x, a11); a11 = fmaf(w.y, hv1.y, a11);
            w = w0k [2 * GS + kk]; a12 = fmaf(w.x, hv1.x, a12); a12 = fmaf(w.y, hv1.y, a12);
            w = w0k [3 * GS + kk]; a13 = fmaf(w.x, hv1.x, a13); a13 = fmaf(w.y, hv1.y, a13);
            w = wh1k[kk];          a20 = fmaf(w.x, hv2.x, a20); a20 = fmaf(w.y, hv2.y, a20);
            w = wh1k[GS     + kk]; a21 = fmaf(w.x, hv2.x, a21); a21 = fmaf(w.y, hv2.y, a21);
            w = wh1k[2 * GS + kk]; a22 = fmaf(w.x, hv2.x, a22); a22 = fmaf(w.y, hv2.y, a22);
            w = wh1k[3 * GS + kk]; a23 = fmaf(w.x, hv2.x, a23); a23 = fmaf(w.y, hv2.y, a23);
        }

        // layer-1 gate math, update c1/h1
        float i1 = fsigm(a10), f1 = fsigm(a11), g1 = ftanh(a12), o1 = fsigm(a13);
        c1 = fmaf(f1, c1, i1 * g1);
        float h1n = o1 * ftanh(c1);

        __syncthreads();                 // all Phase-A reads of h1s/h2s complete
        h1s[b * HS + k] = h1n;
        __syncthreads();                 // h1 (t) visible

        // Phase C: layer-2 input matvec over fresh h1
        #pragma unroll 5
        for (int kk = 0; kk < HID / 2; kk++) {
            float2 hv = h1v[kk];
            float2 w;
            w = wi1k[kk];          a20 = fmaf(w.x, hv.x, a20); a20 = fmaf(w.y, hv.y, a20);
            w = wi1k[GS     + kk]; a21 = fmaf(w.x, hv.x, a21); a21 = fmaf(w.y, hv.y, a21);
            w = wi1k[2 * GS + kk]; a22 = fmaf(w.x, hv.x, a22); a22 = fmaf(w.y, hv.y, a22);
            w = wi1k[3 * GS + kk]; a23 = fmaf(w.x, hv.x, a23); a23 = fmaf(w.y, hv.y, a23);
        }

        float i2 = fsigm(a20), f2 = fsigm(a21), g2 = ftanh(a22), o2 = fsigm(a23);
        c2 = fmaf(f2, c2, i2 * g2);
        float h2n = o2 * ftanh(c2);
        h2s[b * HS + k] = h2n;
        __syncthreads();                 // h2 (t) visible before next step's Phase A
    }

    // ---- epilogue: out[b] = h2_last . fc_W + fc_b ----
    if (k == 0) {
        float acc = fc_b[0];
        #pragma unroll
        for (int kk = 0; kk < HID; kk++)
            acc = fmaf(h2s[b * HS + kk], fc_W[kk], acc);
        out[bg + b] = acc;
    }
}

extern "C" void kernel_launch(void* const* d_in, const int* in_sizes, int n_in,
                              void* d_out, int out_size)
{
    const float* x     = (const float*)d_in[0];
    const float* W_ih0 = (const float*)d_in[1];
    const float* W_hh0 = (const float*)d_in[2];
    const float* b_ih0 = (const float*)d_in[3];
    const float* b_hh0 = (const float*)d_in[4];
    const float* W_ih1 = (const float*)d_in[5];
    const float* W_hh1 = (const float*)d_in[6];
    const float* b_ih1 = (const float*)d_in[7];
    const float* b_hh1 = (const float*)d_in[8];
    const float* fc_W  = (const float*)d_in[9];
    const float* fc_b  = (const float*)d_in[10];
    float* out = (float*)d_out;

    const int smem_bytes = (3 * 200 * WS + BT * SEQL + 2 * BT * HS) * (int)sizeof(float);
    cudaFuncSetAttribute(lstm2_kernel, cudaFuncAttributeMaxDynamicSharedMemorySize, smem_bytes);
    lstm2_kernel<<<NBATCH / BT, NTH, smem_bytes>>>(
        x, W_ih0, W_hh0, b_ih0, b_hh0,
        W_ih1, W_hh1, b_ih1, b_hh1, fc_W, fc_b, out);
}